// round 15
// baseline (speedup 1.0000x reference)
#include <cuda_runtime.h>
#include <math.h>

#define L_TOTAL 32768
#define DMODEL  1024
#define NCHUNK  1024
#define L_PER   (L_TOTAL / NCHUNK)     // 32
#define GROUPS  64
#define CH_PER_G (NCHUNK / GROUPS)     // 16
#define THREADS1 256

// Scratch (allocation-free rule: __device__ globals)
__device__ float g_partials[NCHUNK * DMODEL];    // 4 MB
__device__ float g_partials2[GROUPS * DMODEL];   // 256 KB
__device__ float g_signal[DMODEL];               // 4 KB

// Kernel 1: partial sin-sums over a 32-position chunk of L, all 1024 d.
// Per (thread, l): one __sincosf seeds sin/cos at phase(d); the 3 sibling
// d's (d+256, d+512, d+768) come from FMA rotations with per-l precomputed
// cos/sin phase offsets -> MUFU and FMA pipes balanced (2 MUFU + 8 FMA).
__global__ void __launch_bounds__(THREADS1)
sin_partial_kernel(const float* __restrict__ x) {
    // per l: [a, c, cos1, sin1] and [cos2, sin2, cos3, sin3]
    __shared__ float4 sd[L_PER][2];
    const int chunk = blockIdx.x;
    const int l0 = chunk * L_PER;
    const int tid = threadIdx.x;

    if (tid < L_PER) {
        const float xv = x[l0 + tid];
        const float a  = 6.28318530717958647692f * xv;      // 2*pi*x[l]
        const float p  = logf(1.0f + (float)(l0 + tid));    // log1p(l)
        const float c  = a * p;
        const float dt = 256.0f / 1023.0f;                  // d-offset step in t
        float s1, c1, s2, c2, s3, c3;
        __sincosf(a * dt,        &s1, &c1);
        __sincosf(a * (2.f*dt),  &s2, &c2);
        __sincosf(a * (3.f*dt),  &s3, &c3);
        sd[tid][0] = make_float4(a, c, c1, s1);
        sd[tid][1] = make_float4(c2, s2, c3, s3);
    }
    __syncthreads();

    const float t0 = (float)tid * (1.0f / 1023.0f);

    float acc0 = 0.f, acc1 = 0.f, acc2 = 0.f, acc3 = 0.f;

    #pragma unroll
    for (int l = 0; l < L_PER; ++l) {
        const float4 A = sd[l][0];       // a, c, cos1, sin1  (warp-uniform broadcast)
        const float4 B = sd[l][1];       // cos2, sin2, cos3, sin3
        const float ph = fmaf(A.x, t0, A.y);
        float s, cph;
        __sincosf(ph, &s, &cph);         // 2 MUFU
        acc0 += s;
        acc1 = fmaf(s, A.z, acc1);  acc1 = fmaf(cph, A.w, acc1);
        acc2 = fmaf(s, B.x, acc2);  acc2 = fmaf(cph, B.y, acc2);
        acc3 = fmaf(s, B.z, acc3);  acc3 = fmaf(cph, B.w, acc3);
    }

    float* out = g_partials + chunk * DMODEL;
    out[tid      ] = acc0;
    out[tid + 256] = acc1;
    out[tid + 512] = acc2;
    out[tid + 768] = acc3;
}

// Kernel 2 (stage 1): sum 16 chunks per group. grid=(4,64)=256 blocks.
// Coalesced across threads, deterministic fixed order per output.
__global__ void __launch_bounds__(256)
reduce1_kernel() {
    const int d = blockIdx.x * 256 + threadIdx.x;
    const int g = blockIdx.y;
    const float* src = g_partials + (g * CH_PER_G) * DMODEL + d;
    float s = 0.f;
    #pragma unroll
    for (int c = 0; c < CH_PER_G; ++c)
        s += src[c * DMODEL];
    g_partials2[g * DMODEL + d] = s;
}

// Kernel 3 (stage 2): 1 block x 1024 threads -> g_signal[1024]. 256KB from L2.
__global__ void __launch_bounds__(1024)
reduce2_kernel() {
    const int d = threadIdx.x;
    float s = 0.f;
    #pragma unroll
    for (int g = 0; g < GROUPS; ++g)
        s += g_partials2[g * DMODEL + d];
    g_signal[d] = s;
}

// Kernel 4: matvec, one block per output row. Each of 256 threads loads one
// float4 of W (DRAM) and one float4 of signal (L2 broadcast), then a
// fixed-order tree reduction (shuffle + smem) -> deterministic.
__global__ void __launch_bounds__(256)
matvec_kernel(const float* __restrict__ W, const float* __restrict__ b,
              float* __restrict__ out) {
    __shared__ float swarp[8];
    const int row  = blockIdx.x;
    const int tid  = threadIdx.x;
    const int lane = tid & 31;
    const int warp = tid >> 5;

    const float4 w4 = ((const float4*)(W + row * DMODEL))[tid];
    const float4 s4 = ((const float4*)g_signal)[tid];

    float s = w4.x * s4.x;
    s = fmaf(w4.y, s4.y, s);
    s = fmaf(w4.z, s4.z, s);
    s = fmaf(w4.w, s4.w, s);

    #pragma unroll
    for (int o = 16; o > 0; o >>= 1)
        s += __shfl_down_sync(0xffffffffu, s, o);
    if (lane == 0) swarp[warp] = s;
    __syncthreads();

    if (warp == 0) {
        float v = (lane < 8) ? swarp[lane] : 0.f;
        #pragma unroll
        for (int o = 4; o > 0; o >>= 1)
            v += __shfl_down_sync(0xffffffffu, v, o);
        if (lane == 0)
            out[row] = v + b[row];
    }
}

extern "C" void kernel_launch(void* const* d_in, const int* in_sizes, int n_in,
                              void* d_out, int out_size) {
    const float* x = (const float*)d_in[0];   // inputs [32768]
    const float* W = (const float*)d_in[1];   // W [1024,1024] row-major
    const float* b = (const float*)d_in[2];   // b [1024]
    float* out = (float*)d_out;               // [1024] float32

    sin_partial_kernel<<<NCHUNK, THREADS1>>>(x);

    dim3 rgrid(DMODEL / 256, GROUPS);
    reduce1_kernel<<<rgrid, 256>>>();
    reduce2_kernel<<<1, 1024>>>();

    matvec_kernel<<<DMODEL, 256>>>(W, b, out);
}

// round 16
// speedup vs baseline: 1.0636x; 1.0636x over previous
#include <cuda_runtime.h>
#include <math.h>

#define L_TOTAL 32768
#define DMODEL  1024
#define NCHUNK  1024
#define L_PER   (L_TOTAL / NCHUNK)     // 32
#define GROUPS  64
#define CH_PER_G (NCHUNK / GROUPS)     // 16
#define THREADS1 256
#define ROWS_PER_BLK 8

// Scratch (allocation-free rule: __device__ globals)
__device__ float g_partials[NCHUNK * DMODEL];    // 4 MB
__device__ float g_partials2[GROUPS * DMODEL];   // 256 KB
__device__ float g_signal[DMODEL];               // 4 KB

// Kernel 1: partial sin-sums over a 32-position chunk of L, all 1024 d.
// Per (thread, l): one __sincosf seeds sin/cos at phase(d); the 3 sibling
// d's (d+256, d+512, d+768) come from FMA rotations with per-l precomputed
// cos/sin phase offsets -> MUFU and FMA pipes balanced (2 MUFU + 8 FMA).
__global__ void __launch_bounds__(THREADS1)
sin_partial_kernel(const float* __restrict__ x) {
    // per l: [a, c, cos1, sin1] and [cos2, sin2, cos3, sin3]
    __shared__ float4 sd[L_PER][2];
    const int chunk = blockIdx.x;
    const int l0 = chunk * L_PER;
    const int tid = threadIdx.x;

    if (tid < L_PER) {
        const float xv = x[l0 + tid];
        const float a  = 6.28318530717958647692f * xv;      // 2*pi*x[l]
        const float p  = logf(1.0f + (float)(l0 + tid));    // log1p(l)
        const float c  = a * p;
        const float dt = 256.0f / 1023.0f;                  // d-offset step in t
        float s1, c1, s2, c2, s3, c3;
        __sincosf(a * dt,        &s1, &c1);
        __sincosf(a * (2.f*dt),  &s2, &c2);
        __sincosf(a * (3.f*dt),  &s3, &c3);
        sd[tid][0] = make_float4(a, c, c1, s1);
        sd[tid][1] = make_float4(c2, s2, c3, s3);
    }
    __syncthreads();

    const float t0 = (float)tid * (1.0f / 1023.0f);

    float acc0 = 0.f, acc1 = 0.f, acc2 = 0.f, acc3 = 0.f;

    #pragma unroll
    for (int l = 0; l < L_PER; ++l) {
        const float4 A = sd[l][0];       // a, c, cos1, sin1  (warp-uniform broadcast)
        const float4 B = sd[l][1];       // cos2, sin2, cos3, sin3
        const float ph = fmaf(A.x, t0, A.y);
        float s, cph;
        __sincosf(ph, &s, &cph);         // 2 MUFU
        acc0 += s;
        acc1 = fmaf(s, A.z, acc1);  acc1 = fmaf(cph, A.w, acc1);
        acc2 = fmaf(s, B.x, acc2);  acc2 = fmaf(cph, B.y, acc2);
        acc3 = fmaf(s, B.z, acc3);  acc3 = fmaf(cph, B.w, acc3);
    }

    float* out = g_partials + chunk * DMODEL;
    out[tid      ] = acc0;
    out[tid + 256] = acc1;
    out[tid + 512] = acc2;
    out[tid + 768] = acc3;
}

// Kernel 2 (stage 1): sum 16 chunks per group. grid=(4,64)=256 blocks.
// Coalesced across threads, deterministic fixed order per output. MLP=16.
__global__ void __launch_bounds__(256)
reduce1_kernel() {
    const int d = blockIdx.x * 256 + threadIdx.x;
    const int g = blockIdx.y;
    const float* src = g_partials + (g * CH_PER_G) * DMODEL + d;
    float s = 0.f;
    #pragma unroll
    for (int c = 0; c < CH_PER_G; ++c)
        s += src[c * DMODEL];
    g_partials2[g * DMODEL + d] = s;
}

// Kernel 3 (stage 2): 4 blocks x 256 -> g_signal[1024]. 256KB from L2, MLP=64.
__global__ void __launch_bounds__(256)
reduce2_kernel() {
    const int d = blockIdx.x * 256 + threadIdx.x;
    float s = 0.f;
    #pragma unroll
    for (int g = 0; g < GROUPS; ++g)
        s += g_partials2[g * DMODEL + d];
    g_signal[d] = s;
}

// Kernel 4: matvec, 8 rows per block (128 blocks). Each thread loads its
// signal float4 once, then 8 independent W float4 loads (MLP=8), producing
// 8 row-partials -> smem -> one warp per row does a fixed-order tree
// reduction (deterministic).
__global__ void __launch_bounds__(256)
matvec_kernel(const float* __restrict__ W, const float* __restrict__ b,
              float* __restrict__ out) {
    __shared__ float sp[ROWS_PER_BLK][256];
    const int tid  = threadIdx.x;
    const int row0 = blockIdx.x * ROWS_PER_BLK;

    const float4 s4 = ((const float4*)g_signal)[tid];

    float4 w4[ROWS_PER_BLK];
    #pragma unroll
    for (int r = 0; r < ROWS_PER_BLK; ++r)
        w4[r] = ((const float4*)(W + (row0 + r) * DMODEL))[tid];   // MLP=8

    #pragma unroll
    for (int r = 0; r < ROWS_PER_BLK; ++r) {
        float s = w4[r].x * s4.x;
        s = fmaf(w4[r].y, s4.y, s);
        s = fmaf(w4[r].z, s4.z, s);
        s = fmaf(w4[r].w, s4.w, s);
        sp[r][tid] = s;
    }
    __syncthreads();

    const int warp = tid >> 5;      // warp r reduces row r
    const int lane = tid & 31;
    {
        const float* p = sp[warp];
        float s = p[lane];
        #pragma unroll
        for (int k = 1; k < 8; ++k)           // 256 values, fixed order
            s += p[k * 32 + lane];
        #pragma unroll
        for (int o = 16; o > 0; o >>= 1)
            s += __shfl_down_sync(0xffffffffu, s, o);
        if (lane == 0)
            out[row0 + warp] = s + b[row0 + warp];
    }
}

extern "C" void kernel_launch(void* const* d_in, const int* in_sizes, int n_in,
                              void* d_out, int out_size) {
    const float* x = (const float*)d_in[0];   // inputs [32768]
    const float* W = (const float*)d_in[1];   // W [1024,1024] row-major
    const float* b = (const float*)d_in[2];   // b [1024]
    float* out = (float*)d_out;               // [1024] float32

    sin_partial_kernel<<<NCHUNK, THREADS1>>>(x);

    dim3 rgrid(DMODEL / 256, GROUPS);
    reduce1_kernel<<<rgrid, 256>>>();
    reduce2_kernel<<<4, 256>>>();

    matvec_kernel<<<DMODEL / ROWS_PER_BLK, 256>>>(W, b, out);
}